// round 2
// baseline (speedup 1.0000x reference)
#include <cuda_runtime.h>
#include <math.h>

// ---------------------------------------------------------------------------
// CLIP ViT-B/16 forward. B=32, C=3, IMG=224, P=16 -> 196 patches + cls = 197
// D=768, DEPTH=12, H=12, DH=64, MLP=3072, PROJ=512, NCLS=1000
// ---------------------------------------------------------------------------

#define BB      32
#define NTOK    197
#define NPAT    196
#define DD      768
#define DEPTH   12
#define NH      12
#define DH      64
#define MLPD    3072
#define PROJD   512
#define NCLS    1000
#define MROWS   (BB*NTOK)          // 6304
#define PROWS   (BB*NPAT)          // 6272

// scratch (device globals: allocated at module load, not in kernel_launch)
__device__ float g_x   [MROWS*DD];      // residual stream
__device__ float g_h   [MROWS*DD];      // LN output
__device__ float g_qkv [MROWS*3*DD];    // qkv
__device__ float g_o   [MROWS*DD];      // attention out / patch-embed out
__device__ float g_mlp [MROWS*MLPD];    // mlp hidden
__device__ float g_pat [PROWS*DD];      // im2col patches
__device__ float g_cls [BB*DD];
__device__ float g_z   [BB*PROJD];

// ---------------------------------------------------------------------------
// im2col: gather 16x16x3 patches -> (6272, 768), k = c*256 + r*16 + col
// ---------------------------------------------------------------------------
__global__ void im2col_kernel(const float* __restrict__ x) {
    int idx = blockIdx.x * 256 + threadIdx.x;
    if (idx >= PROWS * DD) return;
    int k = idx % DD;
    int m = idx / DD;
    int b = m / NPAT, p = m % NPAT;
    int ph = p / 14, pw = p % 14;
    int c = k >> 8, r = (k >> 4) & 15, col = k & 15;
    g_pat[idx] = x[(((long)(b*3 + c)*224 + ph*16 + r)*224) + pw*16 + col];
}

// ---------------------------------------------------------------------------
// assemble tokens: y[b,0,:] = cls + pos[0]; y[b,n,:] = pe[b,n-1,:] + pos[n]
// ---------------------------------------------------------------------------
__global__ void assemble_kernel(const float* __restrict__ pe,
                                const float* __restrict__ cls_tok,
                                const float* __restrict__ pos) {
    int idx = blockIdx.x * 256 + threadIdx.x;
    if (idx >= MROWS * DD) return;
    int d = idx % DD;
    int bn = idx / DD;
    int b = bn / NTOK, n = bn % NTOK;
    float v;
    if (n == 0) v = cls_tok[d] + pos[d];
    else        v = pe[((long)b*NPAT + (n-1))*DD + d] + pos[(long)n*DD + d];
    g_h[idx] = v;
}

// ---------------------------------------------------------------------------
// LayerNorm over 768: one block per row, 256 threads * 3 elems
// ---------------------------------------------------------------------------
__global__ void ln_kernel(const float* __restrict__ in, float* __restrict__ out,
                          const float* __restrict__ gam, const float* __restrict__ bet,
                          long in_stride, long out_stride) {
    __shared__ float red[8];
    int row = blockIdx.x, tid = threadIdx.x;
    const float* xr = in + (long)row * in_stride;
    float v0 = xr[tid], v1 = xr[tid + 256], v2 = xr[tid + 512];
    float s = v0 + v1 + v2;
    #pragma unroll
    for (int o = 16; o; o >>= 1) s += __shfl_xor_sync(0xffffffffu, s, o);
    if ((tid & 31) == 0) red[tid >> 5] = s;
    __syncthreads();
    float tot = red[0]+red[1]+red[2]+red[3]+red[4]+red[5]+red[6]+red[7];
    float mean = tot * (1.0f / 768.0f);
    float d0 = v0 - mean, d1 = v1 - mean, d2 = v2 - mean;
    float q = d0*d0 + d1*d1 + d2*d2;
    __syncthreads();
    #pragma unroll
    for (int o = 16; o; o >>= 1) q += __shfl_xor_sync(0xffffffffu, q, o);
    if ((tid & 31) == 0) red[tid >> 5] = q;
    __syncthreads();
    float var = (red[0]+red[1]+red[2]+red[3]+red[4]+red[5]+red[6]+red[7]) * (1.0f/768.0f);
    float rs = rsqrtf(var + 1e-5f);
    float* orow = out + (long)row * out_stride;
    orow[tid      ] = d0 * rs * gam[tid      ] + bet[tid      ];
    orow[tid + 256] = d1 * rs * gam[tid + 256] + bet[tid + 256];
    orow[tid + 512] = d2 * rs * gam[tid + 512] + bet[tid + 512];
}

// ---------------------------------------------------------------------------
// Generic NT SGEMM: C[M,N] = A[M,K] @ W[N,K]^T (+bias) (+residual) (gelu?)
// 64x64 tile, BK=16, 256 threads, 4x4 per thread
// ---------------------------------------------------------------------------
__device__ __forceinline__ float gelu_f(float v) {
    return 0.5f * v * (1.0f + erff(v * 0.70710678118654752f));
}

template<bool GELU, bool RES>
__global__ void gemm_nt(const float* __restrict__ A, const float* __restrict__ W,
                        const float* __restrict__ bias, const float* __restrict__ Rs,
                        float* __restrict__ C, int M, int N, int K) {
    __shared__ float As[16][64];
    __shared__ float Bs[16][64];
    int tid = threadIdx.x;
    int tx = tid & 15, ty = tid >> 4;
    int m0 = blockIdx.y * 64, n0 = blockIdx.x * 64;
    int lr = tid >> 2;            // 0..63
    int lc = (tid & 3) << 2;      // 0,4,8,12
    float acc[4][4] = {};
    const float* Aptr = A + (long)(m0 + lr) * K + lc;
    const float* Wptr = W + (long)(n0 + lr) * K + lc;
    bool am = (m0 + lr) < M;
    bool wn = (n0 + lr) < N;
    for (int k0 = 0; k0 < K; k0 += 16) {
        float4 av = am ? *(const float4*)(Aptr + k0) : make_float4(0.f,0.f,0.f,0.f);
        float4 wv = wn ? *(const float4*)(Wptr + k0) : make_float4(0.f,0.f,0.f,0.f);
        As[lc+0][lr]=av.x; As[lc+1][lr]=av.y; As[lc+2][lr]=av.z; As[lc+3][lr]=av.w;
        Bs[lc+0][lr]=wv.x; Bs[lc+1][lr]=wv.y; Bs[lc+2][lr]=wv.z; Bs[lc+3][lr]=wv.w;
        __syncthreads();
        #pragma unroll
        for (int kk = 0; kk < 16; kk++) {
            float4 a = *(const float4*)(&As[kk][ty << 2]);
            float4 b = *(const float4*)(&Bs[kk][tx << 2]);
            acc[0][0] += a.x*b.x; acc[0][1] += a.x*b.y; acc[0][2] += a.x*b.z; acc[0][3] += a.x*b.w;
            acc[1][0] += a.y*b.x; acc[1][1] += a.y*b.y; acc[1][2] += a.y*b.z; acc[1][3] += a.y*b.w;
            acc[2][0] += a.z*b.x; acc[2][1] += a.z*b.y; acc[2][2] += a.z*b.z; acc[2][3] += a.z*b.w;
            acc[3][0] += a.w*b.x; acc[3][1] += a.w*b.y; acc[3][2] += a.w*b.z; acc[3][3] += a.w*b.w;
        }
        __syncthreads();
    }
    #pragma unroll
    for (int i = 0; i < 4; i++) {
        int m = m0 + (ty << 2) + i;
        if (m >= M) continue;
        #pragma unroll
        for (int j = 0; j < 4; j++) {
            int n = n0 + (tx << 2) + j;
            if (n >= N) continue;
            float v = acc[i][j];
            if (bias) v += bias[n];
            if (RES)  v += Rs[(long)m * N + n];
            if (GELU) v = gelu_f(v);
            C[(long)m * N + n] = v;
        }
    }
}

// ---------------------------------------------------------------------------
// Fused attention: one block per (b, h). K/V staged in smem (pitch 65).
// qkv layout: [b, n, which*768 + h*64 + d]; out layout: [b, n, h*64 + d]
// ---------------------------------------------------------------------------
#define ATTN_SMEM ((197*65*2 + 64 + 256 + 256 + 16) * 4)

__global__ void attn_kernel(const float* __restrict__ qkv, float* __restrict__ out) {
    int b = blockIdx.x / NH, h = blockIdx.x % NH;
    int tid = threadIdx.x;
    int lane = tid & 31, warp = tid >> 5;
    extern __shared__ float sm[];
    float* Ks  = sm;                 // 197*65
    float* Vs  = Ks + 197*65;        // 197*65
    float* qs  = Vs + 197*65;        // 64
    float* ss  = qs + 64;            // 256
    float* pv  = ss + 256;           // 256
    float* red = pv + 256;           // 16

    const float* base = qkv + (long)b * NTOK * (3*DD) + h * DH;
    for (int idx = tid; idx < NTOK * DH; idx += 256) {
        int j = idx >> 6, d = idx & 63;
        Ks[j*65 + d] = base[(long)j*(3*DD) + DD   + d];
        Vs[j*65 + d] = base[(long)j*(3*DD) + 2*DD + d];
    }
    __syncthreads();

    for (int i = 0; i < NTOK; i++) {
        if (tid < DH) qs[tid] = base[(long)i*(3*DD) + tid];
        __syncthreads();

        float s = -1e30f;
        if (tid < NTOK) {
            float acc = 0.f;
            #pragma unroll 16
            for (int d = 0; d < DH; d++) acc += qs[d] * Ks[tid*65 + d];
            s = acc * 0.125f;   // 1/sqrt(64)
        }
        float mx = s;
        #pragma unroll
        for (int o = 16; o; o >>= 1) mx = fmaxf(mx, __shfl_xor_sync(0xffffffffu, mx, o));
        if (lane == 0) red[warp] = mx;
        __syncthreads();
        float rowmax = red[0];
        #pragma unroll
        for (int w = 1; w < 8; w++) rowmax = fmaxf(rowmax, red[w]);

        float p = (tid < NTOK) ? expf(s - rowmax) : 0.f;
        ss[tid] = p;
        float sum = p;
        #pragma unroll
        for (int o = 16; o; o >>= 1) sum += __shfl_xor_sync(0xffffffffu, sum, o);
        if (lane == 0) red[8 + warp] = sum;
        __syncthreads();
        float tot = red[8];
        #pragma unroll
        for (int w = 1; w < 8; w++) tot += red[8 + w];
        float inv = 1.0f / tot;

        int d = tid & 63, jg = tid >> 6;
        float acc = 0.f;
        for (int j = jg; j < NTOK; j += 4) acc += ss[j] * Vs[j*65 + d];
        pv[tid] = acc;
        __syncthreads();
        if (tid < DH) {
            float ov = (pv[tid] + pv[tid+64] + pv[tid+128] + pv[tid+192]) * inv;
            out[((long)b*NTOK + i)*DD + h*DH + tid] = ov;
        }
        __syncthreads();   // protect qs/ss/pv/red for next iteration
    }
}

// ---------------------------------------------------------------------------
// host orchestration
// ---------------------------------------------------------------------------
extern "C" void kernel_launch(void* const* d_in, const int* in_sizes, int n_in,
                              void* d_out, int out_size) {
    const float* x_in    = (const float*)d_in[0];
    const float* conv_w  = (const float*)d_in[1];
    const float* cls_tok = (const float*)d_in[2];
    const float* pos     = (const float*)d_in[3];
    const float* lnprew  = (const float*)d_in[4];
    const float* lnpreb  = (const float*)d_in[5];
    const float* ln1w    = (const float*)d_in[6];
    const float* ln1b    = (const float*)d_in[7];
    const float* qkvw    = (const float*)d_in[8];
    const float* qkvb    = (const float*)d_in[9];
    const float* pw      = (const float*)d_in[10];
    const float* pb      = (const float*)d_in[11];
    const float* ln2w    = (const float*)d_in[12];
    const float* ln2b    = (const float*)d_in[13];
    const float* fw      = (const float*)d_in[14];
    const float* fb      = (const float*)d_in[15];
    const float* cw      = (const float*)d_in[16];
    const float* cb      = (const float*)d_in[17];
    const float* lnpostw = (const float*)d_in[18];
    const float* lnpostb = (const float*)d_in[19];
    const float* projw   = (const float*)d_in[20];
    const float* headw   = (const float*)d_in[21];
    const float* headb   = (const float*)d_in[22];

    float *gx, *gh, *gq, *go, *gm, *gp, *gc, *gz;
    cudaGetSymbolAddress((void**)&gx, g_x);
    cudaGetSymbolAddress((void**)&gh, g_h);
    cudaGetSymbolAddress((void**)&gq, g_qkv);
    cudaGetSymbolAddress((void**)&go, g_o);
    cudaGetSymbolAddress((void**)&gm, g_mlp);
    cudaGetSymbolAddress((void**)&gp, g_pat);
    cudaGetSymbolAddress((void**)&gc, g_cls);
    cudaGetSymbolAddress((void**)&gz, g_z);

    cudaFuncSetAttribute(attn_kernel, cudaFuncAttributeMaxDynamicSharedMemorySize, ATTN_SMEM);

    // patch embed
    im2col_kernel<<<(PROWS*DD + 255)/256, 256>>>(x_in);
    gemm_nt<false,false><<<dim3(DD/64, (PROWS+63)/64), 256>>>(gp, conv_w, nullptr, nullptr, go, PROWS, DD, DD);
    assemble_kernel<<<(MROWS*DD + 255)/256, 256>>>(go, cls_tok, pos);
    ln_kernel<<<MROWS, 256>>>(gh, gx, lnprew, lnpreb, DD, DD);

    dim3 gM((6304+63)/64);  // 99
    for (int l = 0; l < DEPTH; l++) {
        // attention sub-block
        ln_kernel<<<MROWS, 256>>>(gx, gh, ln1w + l*DD, ln1b + l*DD, DD, DD);
        gemm_nt<false,false><<<dim3((3*DD)/64, gM.x), 256>>>(
            gh, qkvw + (long)l*3*DD*DD, qkvb + (long)l*3*DD, nullptr, gq, MROWS, 3*DD, DD);
        attn_kernel<<<BB*NH, 256, ATTN_SMEM>>>(gq, go);
        gemm_nt<false,true><<<dim3(DD/64, gM.x), 256>>>(
            go, pw + (long)l*DD*DD, pb + (long)l*DD, gx, gx, MROWS, DD, DD);
        // MLP sub-block
        ln_kernel<<<MROWS, 256>>>(gx, gh, ln2w + l*DD, ln2b + l*DD, DD, DD);
        gemm_nt<true,false><<<dim3(MLPD/64, gM.x), 256>>>(
            gh, fw + (long)l*MLPD*DD, fb + (long)l*MLPD, nullptr, gm, MROWS, MLPD, DD);
        gemm_nt<false,true><<<dim3(DD/64, gM.x), 256>>>(
            gm, cw + (long)l*DD*MLPD, cb + (long)l*DD, gx, gx, MROWS, DD, MLPD);
    }

    // head: ln_post on cls rows only, then proj, then classifier
    ln_kernel<<<BB, 256>>>(gx, gc, lnpostw, lnpostb, (long)NTOK*DD, DD);
    gemm_nt<false,false><<<dim3(PROJD/64, 1), 256>>>(gc, projw, nullptr, nullptr, gz, BB, PROJD, DD);
    gemm_nt<false,false><<<dim3((NCLS+63)/64, 1), 256>>>(gz, headw, headb, nullptr, (float*)d_out, BB, NCLS, PROJD);
}